// round 1
// baseline (speedup 1.0000x reference)
#include <cuda_runtime.h>
#include <cuda_bf16.h>

// ---------------------------------------------------------------------------
// Instant-NGP style: 16-level bilinear grid encode (F=2) -> MLP 32->128->128->1
// Strategy: fused kernel, 1 point/thread, weights in SMEM (broadcast LDS),
// packed fp32x2 FMA (Blackwell FFMA2) for the matvecs, fp32 exact math.
// ---------------------------------------------------------------------------

#define NPTS   2097152
#define NLVL   16
#define GS     513          // R+1
#define HID    128
#define INDIM  32
#define TPB    256

// RES[l] = floor(16 * 2^(l/3))  (growth = (512/16)^(1/15) = 2^(1/3))
__device__ const int kResTab[16] = {16, 20, 25, 32, 40, 50, 64, 80,
                                    101, 128, 161, 203, 256, 322, 406, 512};

// shared layout (floats)
#define SM_W1   0            // 32*128   = 4096
#define SM_W2   4096         // 128*128  = 16384
#define SM_B1   20480        // 128
#define SM_B2   20608        // 128
#define SM_W3   20736        // 128
#define SM_B3   20864        // 4 (pad)
#define SM_FLOATS 20868
#define SM_BYTES  (SM_FLOATS * 4)

typedef unsigned long long u64;

__device__ __forceinline__ u64 ffma2(u64 a, u64 b, u64 c) {
    u64 d;
    asm("fma.rn.f32x2 %0, %1, %2, %3;" : "=l"(d) : "l"(a), "l"(b), "l"(c));
    return d;
}
// replicate a scalar float into both halves of an f32x2 register pair.
// volatile: block CSE across unrolled chunks (would explode live range).
__device__ __forceinline__ u64 pack2(float v) {
    u64 d; unsigned u = __float_as_uint(v);
    asm volatile("mov.b64 %0, {%1, %2};" : "=l"(d) : "r"(u), "r"(u));
    return d;
}
__device__ __forceinline__ void unpack2(u64 v, float& lo, float& hi) {
    unsigned a, b;
    asm("mov.b64 {%0, %1}, %2;" : "=r"(a), "=r"(b) : "l"(v));
    lo = __uint_as_float(a); hi = __uint_as_float(b);
}

__global__ __launch_bounds__(TPB)
void Model_61065845014888_kernel(
    const float* __restrict__ x,
    const float* __restrict__ grids,
    const float* __restrict__ W1, const float* __restrict__ b1,
    const float* __restrict__ W2, const float* __restrict__ b2,
    const float* __restrict__ W3, const float* __restrict__ b3,
    float* __restrict__ out)
{
    extern __shared__ float sm[];
    const int tid = threadIdx.x;

    // ---- stage weights into SMEM (L2-resident, tiny) ----
    #pragma unroll 4
    for (int i = tid; i < 4096; i += TPB)  sm[SM_W1 + i] = W1[i];
    #pragma unroll 8
    for (int i = tid; i < 16384; i += TPB) sm[SM_W2 + i] = W2[i];
    if (tid < 128) {
        sm[SM_B1 + tid] = b1[tid];
        sm[SM_B2 + tid] = b2[tid];
        sm[SM_W3 + tid] = W3[tid];
    }
    if (tid == 0) sm[SM_B3] = b3[0];

    const int p = blockIdx.x * TPB + tid;

    // ---- 16-level bilinear gather (overlaps the weight staging) ----
    const float2 xy = __ldg(reinterpret_cast<const float2*>(x) + p);
    float feat[INDIM];
    #pragma unroll
    for (int l = 0; l < NLVL; l++) {
        const int   ri = kResTab[l];
        const float rf = (float)ri;
        const float fx = xy.x * rf, fy = xy.y * rf;
        const float fxf = floorf(fx), fyf = floorf(fy);
        const float wx = fx - fxf,  wy = fy - fyf;
        int ix0 = min(max((int)fxf, 0), ri);
        int iy0 = min(max((int)fyf, 0), ri);
        int ix1 = min(ix0 + 1, ri);
        int iy1 = min(iy0 + 1, ri);
        const float2* g = reinterpret_cast<const float2*>(grids) + l * (GS * GS);
        const float2 f00 = __ldg(g + ix0 * GS + iy0);
        const float2 f10 = __ldg(g + ix1 * GS + iy0);
        const float2 f01 = __ldg(g + ix0 * GS + iy1);
        const float2 f11 = __ldg(g + ix1 * GS + iy1);
        const float owx = 1.0f - wx, owy = 1.0f - wy;
        const float ax = f00.x * owx + f10.x * wx;
        const float ay = f00.y * owx + f10.y * wx;
        const float bx = f01.x * owx + f11.x * wx;
        const float by = f01.y * owx + f11.y * wx;
        feat[2 * l + 0] = ax * owy + bx * wy;
        feat[2 * l + 1] = ay * owy + by * wy;
    }

    __syncthreads();   // weights staged

    // ---- layer 1: h1 = relu(feat @ W1 + b1), packed f32x2 over j ----
    float h1[HID];
    #pragma unroll
    for (int c = 0; c < 4; c++) {               // 4 chunks of 32 output cols
        u64 acc[16];
        const ulonglong2* bb = reinterpret_cast<const ulonglong2*>(sm + SM_B1 + c * 32);
        #pragma unroll
        for (int t = 0; t < 8; t++) { ulonglong2 v = bb[t]; acc[2*t] = v.x; acc[2*t+1] = v.y; }
        #pragma unroll
        for (int k = 0; k < INDIM; k++) {
            const u64 fk = pack2(feat[k]);
            const ulonglong2* w = reinterpret_cast<const ulonglong2*>(sm + SM_W1 + k * HID + c * 32);
            #pragma unroll
            for (int t = 0; t < 8; t++) {
                const ulonglong2 ww = w[t];
                acc[2*t]   = ffma2(fk, ww.x, acc[2*t]);
                acc[2*t+1] = ffma2(fk, ww.y, acc[2*t+1]);
            }
        }
        #pragma unroll
        for (int t = 0; t < 16; t++) {
            float lo, hi; unpack2(acc[t], lo, hi);
            h1[c * 32 + 2*t + 0] = fmaxf(lo, 0.0f);
            h1[c * 32 + 2*t + 1] = fmaxf(hi, 0.0f);
        }
    }

    // ---- layer 2 + layer 3 fused: out = relu(h1 @ W2 + b2) @ W3 + b3 ----
    float outv = sm[SM_B3];
    #pragma unroll
    for (int c = 0; c < 4; c++) {
        u64 acc[16];
        const ulonglong2* bb = reinterpret_cast<const ulonglong2*>(sm + SM_B2 + c * 32);
        #pragma unroll
        for (int t = 0; t < 8; t++) { ulonglong2 v = bb[t]; acc[2*t] = v.x; acc[2*t+1] = v.y; }
        #pragma unroll
        for (int k = 0; k < HID; k++) {
            const u64 hk = pack2(h1[k]);
            const ulonglong2* w = reinterpret_cast<const ulonglong2*>(sm + SM_W2 + k * HID + c * 32);
            #pragma unroll
            for (int t = 0; t < 8; t++) {
                const ulonglong2 ww = w[t];
                acc[2*t]   = ffma2(hk, ww.x, acc[2*t]);
                acc[2*t+1] = ffma2(hk, ww.y, acc[2*t+1]);
            }
        }
        #pragma unroll
        for (int t = 0; t < 16; t++) {
            float lo, hi; unpack2(acc[t], lo, hi);
            outv += fmaxf(lo, 0.0f) * sm[SM_W3 + c * 32 + 2*t]
                  + fmaxf(hi, 0.0f) * sm[SM_W3 + c * 32 + 2*t + 1];
        }
    }

    out[p] = outv;
}

extern "C" void kernel_launch(void* const* d_in, const int* in_sizes, int n_in,
                              void* d_out, int out_size)
{
    const float* x     = (const float*)d_in[0];
    const float* grids = (const float*)d_in[1];
    const float* W1    = (const float*)d_in[2];
    const float* b1    = (const float*)d_in[3];
    const float* W2    = (const float*)d_in[4];
    const float* b2    = (const float*)d_in[5];
    const float* W3    = (const float*)d_in[6];
    const float* b3    = (const float*)d_in[7];
    float* out = (float*)d_out;

    (void)in_sizes; (void)n_in; (void)out_size;

    cudaFuncSetAttribute(Model_61065845014888_kernel,
                         cudaFuncAttributeMaxDynamicSharedMemorySize, SM_BYTES);

    Model_61065845014888_kernel<<<NPTS / TPB, TPB, SM_BYTES>>>(
        x, grids, W1, b1, W2, b2, W3, b3, out);
}

// round 3
// speedup vs baseline: 1.3556x; 1.3556x over previous
#include <cuda_runtime.h>
#include <cstdint>

// ---------------------------------------------------------------------------
// Instant-NGP MLP, register-tiled FFMA2 GEMM (no tcgen05: harness PTX target
// is compute_103 which blocks all sm_103a-gated instructions).
// Persistent CTAs + atomic tile queue. Tile = 128 points.
// Thread tile = 8 points x 8 cols, packed f32x2 FMA.
// ---------------------------------------------------------------------------

#define NPTS    2097152
#define NTILES  (NPTS / 128)     // 16384
#define TPB     256
#define NCTA    192
#define GS      513

// SMEM layout in floats
#define SM_W1   0                 // 32*128   = 4096
#define SM_W2   4096              // 128*128  = 16384
#define SM_FEAT 20480             // 128*36   = 4608  (row pad 36)
#define SM_H1   25088             // 128*132  = 16896 (row pad 132)
#define SM_B1   41984             // 128
#define SM_B2   42112             // 128
#define SM_W3   42240             // 128
#define SM_B3   42368             // 1 (+pad)
#define SM_PART 42376             // 128*17 = 2176
#define SM_TILE 44552             // broadcast slot (int)
#define SM_FLOATS 44556
#define SMEM_BYTES (SM_FLOATS * 4)

typedef unsigned long long u64;

__device__ int g_tile_ctr;

__device__ const int kResTab[16] = {16, 20, 25, 32, 40, 50, 64, 80,
                                    101, 128, 161, 203, 256, 322, 406, 512};

__device__ __forceinline__ u64 ffma2(u64 a, u64 b, u64 c) {
    u64 d;
    asm("fma.rn.f32x2 %0, %1, %2, %3;" : "=l"(d) : "l"(a), "l"(b), "l"(c));
    return d;
}
__device__ __forceinline__ u64 pack2(float v) {
    u64 d; unsigned u = __float_as_uint(v);
    asm volatile("mov.b64 %0, {%1, %2};" : "=l"(d) : "r"(u), "r"(u));
    return d;
}
__device__ __forceinline__ void unpack2(u64 v, float& lo, float& hi) {
    unsigned a, b;
    asm("mov.b64 {%0, %1}, %2;" : "=r"(a), "=r"(b) : "l"(v));
    lo = __uint_as_float(a); hi = __uint_as_float(b);
}

// 8-level bilinear gather (levels L0..L0+7) for one point
template <int L0>
__device__ __forceinline__ void gather8(float2 xy, const float* __restrict__ grids,
                                        float* f) {
    #pragma unroll
    for (int i = 0; i < 8; i++) {
        const int   ri = kResTab[L0 + i];
        const float rf = (float)ri;
        const float fx = xy.x * rf, fy = xy.y * rf;
        const float fxf = floorf(fx), fyf = floorf(fy);
        const float wx = fx - fxf, wy = fy - fyf;
        int ix0 = min(max((int)fxf, 0), ri);
        int iy0 = min(max((int)fyf, 0), ri);
        int ix1 = min(ix0 + 1, ri);
        int iy1 = min(iy0 + 1, ri);
        const float2* g = reinterpret_cast<const float2*>(grids)
                        + (size_t)(L0 + i) * (GS * GS);
        const float2 f00 = __ldg(g + ix0 * GS + iy0);
        const float2 f10 = __ldg(g + ix1 * GS + iy0);
        const float2 f01 = __ldg(g + ix0 * GS + iy1);
        const float2 f11 = __ldg(g + ix1 * GS + iy1);
        const float owx = 1.0f - wx, owy = 1.0f - wy;
        const float ax = f00.x * owx + f10.x * wx;
        const float ay = f00.y * owx + f10.y * wx;
        const float bx = f01.x * owx + f11.x * wx;
        const float by = f01.y * owx + f11.y * wx;
        f[2 * i + 0] = ax * owy + bx * wy;
        f[2 * i + 1] = ay * owy + by * wy;
    }
}

__global__ void reset_kernel() { g_tile_ctr = 0; }

__global__ __launch_bounds__(TPB, 1)
void Model_61065845014888_kernel(
    const float* __restrict__ x,
    const float* __restrict__ grids,
    const float* __restrict__ W1, const float* __restrict__ b1,
    const float* __restrict__ W2, const float* __restrict__ b2,
    const float* __restrict__ W3, const float* __restrict__ b3,
    float* __restrict__ out)
{
    extern __shared__ float sm[];
    const int tid = threadIdx.x;

    // ---- stage weights once ----
    {
        const float4* s4 = reinterpret_cast<const float4*>(W1);
        float4*       d4 = reinterpret_cast<float4*>(sm + SM_W1);
        #pragma unroll 2
        for (int i = tid; i < 1024; i += TPB) d4[i] = s4[i];
    }
    {
        const float4* s4 = reinterpret_cast<const float4*>(W2);
        float4*       d4 = reinterpret_cast<float4*>(sm + SM_W2);
        #pragma unroll 4
        for (int i = tid; i < 4096; i += TPB) d4[i] = s4[i];
    }
    if (tid < 128) {
        sm[SM_B1 + tid] = b1[tid];
        sm[SM_B2 + tid] = b2[tid];
        sm[SM_W3 + tid] = W3[tid];
    }
    if (tid == 0) sm[SM_B3] = b3[0];

    const int pg = tid >> 4;          // point group 0..15 (8 pts each)
    const int cg = tid & 15;          // col group 0..15 (8 cols each)
    const int j0 = cg * 8;
    const int p0 = pg * 8;

    // gather role: 2 threads per point
    const int gpt   = tid >> 1;       // 0..127
    const int ghalf = tid & 1;        // levels 0-7 or 8-15

    __syncthreads();

    for (;;) {
        // ---- grab a tile from the global queue ----
        if (tid == 0)
            reinterpret_cast<int*>(sm)[SM_TILE] = atomicAdd(&g_tile_ctr, 1);
        __syncthreads();
        const int tile = reinterpret_cast<int*>(sm)[SM_TILE];
        if (tile >= NTILES) break;

        // ================= gather -> feat[pt][36] =================
        {
            const int p = tile * 128 + gpt;
            const float2 xy = __ldg(reinterpret_cast<const float2*>(x) + p);
            float f[16];
            if (ghalf == 0) gather8<0>(xy, grids, f);
            else            gather8<8>(xy, grids, f);
            float4* dst = reinterpret_cast<float4*>(sm + SM_FEAT + gpt * 36 + ghalf * 16);
            dst[0] = make_float4(f[0],  f[1],  f[2],  f[3]);
            dst[1] = make_float4(f[4],  f[5],  f[6],  f[7]);
            dst[2] = make_float4(f[8],  f[9],  f[10], f[11]);
            dst[3] = make_float4(f[12], f[13], f[14], f[15]);
        }
        __syncthreads();

        // ================= GEMM1: h1 = relu(feat @ W1 + b1) =================
        u64 acc[8][4];
        {
            const ulonglong2 bv0 = *reinterpret_cast<const ulonglong2*>(sm + SM_B1 + j0);
            const ulonglong2 bv1 = *reinterpret_cast<const ulonglong2*>(sm + SM_B1 + j0 + 4);
            #pragma unroll
            for (int p = 0; p < 8; p++) {
                acc[p][0] = bv0.x; acc[p][1] = bv0.y;
                acc[p][2] = bv1.x; acc[p][3] = bv1.y;
            }
            #pragma unroll 1
            for (int kb = 0; kb < 8; kb++) {
                float4 av[8];
                #pragma unroll
                for (int p = 0; p < 8; p++)
                    av[p] = *reinterpret_cast<const float4*>(
                        sm + SM_FEAT + (p0 + p) * 36 + kb * 4);
                #pragma unroll
                for (int kk = 0; kk < 4; kk++) {
                    const int k = kb * 4 + kk;
                    const ulonglong2 w0 = *reinterpret_cast<const ulonglong2*>(
                        sm + SM_W1 + k * 128 + j0);
                    const ulonglong2 w1 = *reinterpret_cast<const ulonglong2*>(
                        sm + SM_W1 + k * 128 + j0 + 4);
                    #pragma unroll
                    for (int p = 0; p < 8; p++) {
                        const float* af = reinterpret_cast<const float*>(&av[p]);
                        const u64 a = pack2(af[kk]);
                        acc[p][0] = ffma2(a, w0.x, acc[p][0]);
                        acc[p][1] = ffma2(a, w0.y, acc[p][1]);
                        acc[p][2] = ffma2(a, w1.x, acc[p][2]);
                        acc[p][3] = ffma2(a, w1.y, acc[p][3]);
                    }
                }
            }
        }
        // relu + store h1[pt][132]
        #pragma unroll
        for (int p = 0; p < 8; p++) {
            float v[8];
            #pragma unroll
            for (int c = 0; c < 4; c++) unpack2(acc[p][c], v[2*c], v[2*c+1]);
            #pragma unroll
            for (int i = 0; i < 8; i++) v[i] = fmaxf(v[i], 0.0f);
            float4* dst = reinterpret_cast<float4*>(sm + SM_H1 + (p0 + p) * 132 + j0);
            dst[0] = make_float4(v[0], v[1], v[2], v[3]);
            dst[1] = make_float4(v[4], v[5], v[6], v[7]);
        }
        __syncthreads();

        // ================= GEMM2: h2 = relu(h1 @ W2 + b2) =================
        {
            const ulonglong2 bv0 = *reinterpret_cast<const ulonglong2*>(sm + SM_B2 + j0);
            const ulonglong2 bv1 = *reinterpret_cast<const ulonglong2*>(sm + SM_B2 + j0 + 4);
            #pragma unroll
            for (int p = 0; p < 8; p++) {
                acc[p][0] = bv0.x; acc[p][1] = bv0.y;
                acc[p][2] = bv1.x; acc[p][3] = bv1.y;
            }
            #pragma unroll 1
            for (int kb = 0; kb < 32; kb++) {
                float4 av[8];
                #pragma unroll
                for (int p = 0; p < 8; p++)
                    av[p] = *reinterpret_cast<const float4*>(
                        sm + SM_H1 + (p0 + p) * 132 + kb * 4);
                #pragma unroll
                for (int kk = 0; kk < 4; kk++) {
                    const int k = kb * 4 + kk;
                    const ulonglong2 w0 = *reinterpret_cast<const ulonglong2*>(
                        sm + SM_W2 + k * 128 + j0);
                    const ulonglong2 w1 = *reinterpret_cast<const ulonglong2*>(
                        sm + SM_W2 + k * 128 + j0 + 4);
                    #pragma unroll
                    for (int p = 0; p < 8; p++) {
                        const float* af = reinterpret_cast<const float*>(&av[p]);
                        const u64 a = pack2(af[kk]);
                        acc[p][0] = ffma2(a, w0.x, acc[p][0]);
                        acc[p][1] = ffma2(a, w0.y, acc[p][1]);
                        acc[p][2] = ffma2(a, w1.x, acc[p][2]);
                        acc[p][3] = ffma2(a, w1.y, acc[p][3]);
                    }
                }
            }
        }
        // relu + layer-3 partial dot: s_p = sum_j relu(h2[p][j]) * W3[j]
        #pragma unroll
        for (int p = 0; p < 8; p++) {
            float s = 0.0f;
            #pragma unroll
            for (int c = 0; c < 4; c++) {
                float lo, hi; unpack2(acc[p][c], lo, hi);
                s = fmaf(fmaxf(lo, 0.0f), sm[SM_W3 + j0 + 2*c],     s);
                s = fmaf(fmaxf(hi, 0.0f), sm[SM_W3 + j0 + 2*c + 1], s);
            }
            sm[SM_PART + (p0 + p) * 17 + cg] = s;
        }
        __syncthreads();

        // ================= reduce 16 partials per point -> out =================
        if (tid < 128) {
            const float* pr = sm + SM_PART + tid * 17;
            float s = sm[SM_B3];
            #pragma unroll
            for (int c = 0; c < 16; c++) s += pr[c];
            out[tile * 128 + tid] = s;
        }
        __syncthreads();
    }
}

extern "C" void kernel_launch(void* const* d_in, const int* in_sizes, int n_in,
                              void* d_out, int out_size)
{
    const float* x     = (const float*)d_in[0];
    const float* grids = (const float*)d_in[1];
    const float* W1    = (const float*)d_in[2];
    const float* b1    = (const float*)d_in[3];
    const float* W2    = (const float*)d_in[4];
    const float* b2    = (const float*)d_in[5];
    const float* W3    = (const float*)d_in[6];
    const float* b3    = (const float*)d_in[7];
    float* out = (float*)d_out;
    (void)in_sizes; (void)n_in; (void)out_size;

    cudaFuncSetAttribute(Model_61065845014888_kernel,
                         cudaFuncAttributeMaxDynamicSharedMemorySize, SMEM_BYTES);

    reset_kernel<<<1, 1>>>();
    Model_61065845014888_kernel<<<NCTA, TPB, SMEM_BYTES>>>(
        x, grids, W1, b1, W2, b2, W3, b3, out);
}

// round 4
// speedup vs baseline: 1.4178x; 1.0459x over previous
#include <cuda_runtime.h>
#include <cstdint>

// ---------------------------------------------------------------------------
// Instant-NGP MLP, register-tiled FFMA2 GEMM, warp-uniform weight broadcast.
// Warp w owns 16 output cols; lane owns 4 points. All weight LDS are
// warp-broadcast (1 crossbar phase); activation LDS conflict-free.
// ---------------------------------------------------------------------------

#define NPTS    2097152
#define NTILES  (NPTS / 128)     // 16384
#define TPB     256
#define NCTA    148
#define GS      513

// SMEM layout in floats
#define SM_W1   0                 // 32*128   = 4096
#define SM_W2   4096              // 128*128  = 16384
#define SM_FEAT 20480             // 128*36   = 4608
#define SM_H1   25088             // 128*132  = 16896
#define SM_B1   41984             // 128
#define SM_B2   42112             // 128
#define SM_W3   42240             // 128
#define SM_B3   42368             // 1 (+7 pad)
#define SM_PART 42376             // 128*9 = 1152
#define SM_TILE 43528             // int slot
#define SM_FLOATS 43532
#define SMEM_BYTES (SM_FLOATS * 4)

typedef unsigned long long u64;

__device__ int g_tile_ctr;

__device__ const int kResTab[16] = {16, 20, 25, 32, 40, 50, 64, 80,
                                    101, 128, 161, 203, 256, 322, 406, 512};

__device__ __forceinline__ u64 ffma2(u64 a, u64 b, u64 c) {
    u64 d;
    asm("fma.rn.f32x2 %0, %1, %2, %3;" : "=l"(d) : "l"(a), "l"(b), "l"(c));
    return d;
}
__device__ __forceinline__ u64 pack2(float v) {
    u64 d; unsigned u = __float_as_uint(v);
    asm volatile("mov.b64 %0, {%1, %2};" : "=l"(d) : "r"(u), "r"(u));
    return d;
}
__device__ __forceinline__ void unpack2(u64 v, float& lo, float& hi) {
    unsigned a, b;
    asm("mov.b64 {%0, %1}, %2;" : "=r"(a), "=r"(b) : "l"(v));
    lo = __uint_as_float(a); hi = __uint_as_float(b);
}

template <int L0>
__device__ __forceinline__ void gather8(float2 xy, const float* __restrict__ grids,
                                        float* f) {
    #pragma unroll
    for (int i = 0; i < 8; i++) {
        const int   ri = kResTab[L0 + i];
        const float rf = (float)ri;
        const float fx = xy.x * rf, fy = xy.y * rf;
        const float fxf = floorf(fx), fyf = floorf(fy);
        const float wx = fx - fxf, wy = fy - fyf;
        int ix0 = min(max((int)fxf, 0), ri);
        int iy0 = min(max((int)fyf, 0), ri);
        int ix1 = min(ix0 + 1, ri);
        int iy1 = min(iy0 + 1, ri);
        const float2* g = reinterpret_cast<const float2*>(grids)
                        + (size_t)(L0 + i) * (GS * GS);
        const float2 f00 = __ldg(g + ix0 * GS + iy0);
        const float2 f10 = __ldg(g + ix1 * GS + iy0);
        const float2 f01 = __ldg(g + ix0 * GS + iy1);
        const float2 f11 = __ldg(g + ix1 * GS + iy1);
        const float owx = 1.0f - wx, owy = 1.0f - wy;
        const float ax = f00.x * owx + f10.x * wx;
        const float ay = f00.y * owx + f10.y * wx;
        const float bx = f01.x * owx + f11.x * wx;
        const float by = f01.y * owx + f11.y * wx;
        f[2 * i + 0] = ax * owy + bx * wy;
        f[2 * i + 1] = ay * owy + by * wy;
    }
}

__global__ void reset_kernel() { g_tile_ctr = 0; }

// one GEMM macro-step: acc[4][8] over 16 cols (j0 warp-uniform), 4 k-values
#define GEMM_KB(SMW, SMACT, PAD)                                              \
    do {                                                                      \
        float4 av[4];                                                         \
        _Pragma("unroll")                                                     \
        for (int i = 0; i < 4; i++)                                           \
            av[i] = *reinterpret_cast<const float4*>(                         \
                sm + (SMACT) + (lane + 32 * i) * (PAD) + kb * 4);             \
        _Pragma("unroll")                                                     \
        for (int kk = 0; kk < 4; kk++) {                                      \
            const float* wrow = sm + (SMW) + (kb * 4 + kk) * 128 + j0;        \
            const ulonglong2 wa = *reinterpret_cast<const ulonglong2*>(wrow);     \
            const ulonglong2 wb = *reinterpret_cast<const ulonglong2*>(wrow + 4); \
            const ulonglong2 wc = *reinterpret_cast<const ulonglong2*>(wrow + 8); \
            const ulonglong2 wd = *reinterpret_cast<const ulonglong2*>(wrow + 12);\
            _Pragma("unroll")                                                 \
            for (int i = 0; i < 4; i++) {                                     \
                const float* af = reinterpret_cast<const float*>(&av[i]);     \
                const u64 a = pack2(af[kk]);                                  \
                acc[i][0] = ffma2(a, wa.x, acc[i][0]);                        \
                acc[i][1] = ffma2(a, wa.y, acc[i][1]);                        \
                acc[i][2] = ffma2(a, wb.x, acc[i][2]);                        \
                acc[i][3] = ffma2(a, wb.y, acc[i][3]);                        \
                acc[i][4] = ffma2(a, wc.x, acc[i][4]);                        \
                acc[i][5] = ffma2(a, wc.y, acc[i][5]);                        \
                acc[i][6] = ffma2(a, wd.x, acc[i][6]);                        \
                acc[i][7] = ffma2(a, wd.y, acc[i][7]);                        \
            }                                                                 \
        }                                                                     \
    } while (0)

__global__ __launch_bounds__(TPB, 1)
void Model_61065845014888_kernel(
    const float* __restrict__ x,
    const float* __restrict__ grids,
    const float* __restrict__ W1, const float* __restrict__ b1,
    const float* __restrict__ W2, const float* __restrict__ b2,
    const float* __restrict__ W3, const float* __restrict__ b3,
    float* __restrict__ out)
{
    extern __shared__ float sm[];
    const int tid = threadIdx.x;

    // ---- stage weights once ----
    {
        const float4* s4 = reinterpret_cast<const float4*>(W1);
        float4*       d4 = reinterpret_cast<float4*>(sm + SM_W1);
        #pragma unroll 2
        for (int i = tid; i < 1024; i += TPB) d4[i] = s4[i];
    }
    {
        const float4* s4 = reinterpret_cast<const float4*>(W2);
        float4*       d4 = reinterpret_cast<float4*>(sm + SM_W2);
        #pragma unroll 4
        for (int i = tid; i < 4096; i += TPB) d4[i] = s4[i];
    }
    if (tid < 128) {
        sm[SM_B1 + tid] = b1[tid];
        sm[SM_B2 + tid] = b2[tid];
        sm[SM_W3 + tid] = W3[tid];
    }
    if (tid == 0) sm[SM_B3] = b3[0];

    const int wid  = tid >> 5;        // warp 0..7 -> col chunk
    const int lane = tid & 31;        // point base
    const int j0   = wid * 16;

    // gather role: 2 threads per point
    const int gpt   = tid >> 1;
    const int ghalf = tid & 1;

    __syncthreads();

    for (;;) {
        if (tid == 0)
            reinterpret_cast<int*>(sm)[SM_TILE] = atomicAdd(&g_tile_ctr, 1);
        __syncthreads();
        const int tile = reinterpret_cast<int*>(sm)[SM_TILE];
        if (tile >= NTILES) break;

        // ================= gather -> feat[pt][36] =================
        {
            const int p = tile * 128 + gpt;
            const float2 xy = __ldg(reinterpret_cast<const float2*>(x) + p);
            float f[16];
            if (ghalf == 0) gather8<0>(xy, grids, f);
            else            gather8<8>(xy, grids, f);
            float4* dst = reinterpret_cast<float4*>(sm + SM_FEAT + gpt * 36 + ghalf * 16);
            dst[0] = make_float4(f[0],  f[1],  f[2],  f[3]);
            dst[1] = make_float4(f[4],  f[5],  f[6],  f[7]);
            dst[2] = make_float4(f[8],  f[9],  f[10], f[11]);
            dst[3] = make_float4(f[12], f[13], f[14], f[15]);
        }
        __syncthreads();

        u64 acc[4][8];

        // ================= GEMM1: h1 = relu(feat @ W1 + b1) =================
        {
            const float* brow = sm + SM_B1 + j0;
            const ulonglong2 ba = *reinterpret_cast<const ulonglong2*>(brow);
            const ulonglong2 bb = *reinterpret_cast<const ulonglong2*>(brow + 4);
            const ulonglong2 bc = *reinterpret_cast<const ulonglong2*>(brow + 8);
            const ulonglong2 bd = *reinterpret_cast<const ulonglong2*>(brow + 12);
            #pragma unroll
            for (int i = 0; i < 4; i++) {
                acc[i][0] = ba.x; acc[i][1] = ba.y;
                acc[i][2] = bb.x; acc[i][3] = bb.y;
                acc[i][4] = bc.x; acc[i][5] = bc.y;
                acc[i][6] = bd.x; acc[i][7] = bd.y;
            }
            #pragma unroll 1
            for (int kb = 0; kb < 8; kb++) GEMM_KB(SM_W1, SM_FEAT, 36);
        }
        // relu + store h1[pt][132]
        #pragma unroll
        for (int i = 0; i < 4; i++) {
            const int p = lane + 32 * i;
            float v[16];
            #pragma unroll
            for (int c = 0; c < 8; c++) unpack2(acc[i][c], v[2*c], v[2*c+1]);
            #pragma unroll
            for (int q = 0; q < 16; q++) v[q] = fmaxf(v[q], 0.0f);
            float4* dst = reinterpret_cast<float4*>(sm + SM_H1 + p * 132 + j0);
            dst[0] = make_float4(v[0],  v[1],  v[2],  v[3]);
            dst[1] = make_float4(v[4],  v[5],  v[6],  v[7]);
            dst[2] = make_float4(v[8],  v[9],  v[10], v[11]);
            dst[3] = make_float4(v[12], v[13], v[14], v[15]);
        }
        __syncthreads();

        // ================= GEMM2: h2 = relu(h1 @ W2 + b2) =================
        {
            const float* brow = sm + SM_B2 + j0;
            const ulonglong2 ba = *reinterpret_cast<const ulonglong2*>(brow);
            const ulonglong2 bb = *reinterpret_cast<const ulonglong2*>(brow + 4);
            const ulonglong2 bc = *reinterpret_cast<const ulonglong2*>(brow + 8);
            const ulonglong2 bd = *reinterpret_cast<const ulonglong2*>(brow + 12);
            #pragma unroll
            for (int i = 0; i < 4; i++) {
                acc[i][0] = ba.x; acc[i][1] = ba.y;
                acc[i][2] = bb.x; acc[i][3] = bb.y;
                acc[i][4] = bc.x; acc[i][5] = bc.y;
                acc[i][6] = bd.x; acc[i][7] = bd.y;
            }
            #pragma unroll 1
            for (int kb = 0; kb < 32; kb++) GEMM_KB(SM_W2, SM_H1, 132);
        }
        // relu + layer-3 partial dot over this warp's 16 cols
        #pragma unroll
        for (int i = 0; i < 4; i++) {
            float s = 0.0f;
            #pragma unroll
            for (int c = 0; c < 8; c++) {
                float lo, hi; unpack2(acc[i][c], lo, hi);
                s = fmaf(fmaxf(lo, 0.0f), sm[SM_W3 + j0 + 2*c],     s);
                s = fmaf(fmaxf(hi, 0.0f), sm[SM_W3 + j0 + 2*c + 1], s);
            }
            sm[SM_PART + (lane + 32 * i) * 9 + wid] = s;
        }
        __syncthreads();

        // ================= reduce 8 warp-partials per point =================
        if (tid < 128) {
            const float* pr = sm + SM_PART + tid * 9;
            float s = sm[SM_B3];
            #pragma unroll
            for (int c = 0; c < 8; c++) s += pr[c];
            out[tile * 128 + tid] = s;
        }
        __syncthreads();
    }
}

extern "C" void kernel_launch(void* const* d_in, const int* in_sizes, int n_in,
                              void* d_out, int out_size)
{
    const float* x     = (const float*)d_in[0];
    const float* grids = (const float*)d_in[1];
    const float* W1    = (const float*)d_in[2];
    const float* b1    = (const float*)d_in[3];
    const float* W2    = (const float*)d_in[4];
    const float* b2    = (const float*)d_in[5];
    const float* W3    = (const float*)d_in[6];
    const float* b3    = (const float*)d_in[7];
    float* out = (float*)d_out;
    (void)in_sizes; (void)n_in; (void)out_size;

    cudaFuncSetAttribute(Model_61065845014888_kernel,
                         cudaFuncAttributeMaxDynamicSharedMemorySize, SMEM_BYTES);

    reset_kernel<<<1, 1>>>();
    Model_61065845014888_kernel<<<NCTA, TPB, SMEM_BYTES>>>(
        x, grids, W1, b1, W2, b2, W3, b3, out);
}

// round 5
// speedup vs baseline: 1.4782x; 1.0426x over previous
#include <cuda_runtime.h>
#include <cstdint>

// ---------------------------------------------------------------------------
// Instant-NGP MLP, register-tiled FFMA2 GEMM, warp-uniform weight broadcast.
// 512 threads/CTA (4 warps/SMSP for latency hiding). Warp owns 8 output cols,
// lane owns 4 points. Weight LDS warp-broadcast; activation LDS conflict-free.
// ---------------------------------------------------------------------------

#define NPTS    2097152
#define NTILES  (NPTS / 128)     // 16384
#define TPB     512
#define NCTA    148
#define GS      513

// SMEM layout in floats
#define SM_W1   0                 // 32*128   = 4096
#define SM_W2   4096              // 128*128  = 16384
#define SM_FEAT 20480             // 128*36   = 4608
#define SM_H1   25088             // 128*132  = 16896
#define SM_B1   41984             // 128
#define SM_B2   42112             // 128
#define SM_W3   42240             // 128
#define SM_B3   42368             // 1 (+7 pad)
#define SM_PART 42376             // 128*17 = 2176
#define SM_TILE 44552             // int slot
#define SM_FLOATS 44556
#define SMEM_BYTES (SM_FLOATS * 4)

typedef unsigned long long u64;

__device__ int g_tile_ctr;

__device__ const int kResTab[16] = {16, 20, 25, 32, 40, 50, 64, 80,
                                    101, 128, 161, 203, 256, 322, 406, 512};

__device__ __forceinline__ u64 ffma2(u64 a, u64 b, u64 c) {
    u64 d;
    asm("fma.rn.f32x2 %0, %1, %2, %3;" : "=l"(d) : "l"(a), "l"(b), "l"(c));
    return d;
}
__device__ __forceinline__ u64 pack2(float v) {
    u64 d; unsigned u = __float_as_uint(v);
    asm volatile("mov.b64 %0, {%1, %2};" : "=l"(d) : "r"(u), "r"(u));
    return d;
}
__device__ __forceinline__ void unpack2(u64 v, float& lo, float& hi) {
    unsigned a, b;
    asm("mov.b64 {%0, %1}, %2;" : "=r"(a), "=r"(b) : "l"(v));
    lo = __uint_as_float(a); hi = __uint_as_float(b);
}

// 4-level bilinear gather, compile-time level base
template <int L0>
__device__ __forceinline__ void gather4(float2 xy, const float* __restrict__ grids,
                                        float* f) {
    #pragma unroll
    for (int i = 0; i < 4; i++) {
        const int   ri = kResTab[L0 + i];
        const float rf = (float)ri;
        const float fx = xy.x * rf, fy = xy.y * rf;
        const float fxf = floorf(fx), fyf = floorf(fy);
        const float wx = fx - fxf, wy = fy - fyf;
        int ix0 = min(max((int)fxf, 0), ri);
        int iy0 = min(max((int)fyf, 0), ri);
        int ix1 = min(ix0 + 1, ri);
        int iy1 = min(iy0 + 1, ri);
        const float2* g = reinterpret_cast<const float2*>(grids)
                        + (size_t)(L0 + i) * (GS * GS);
        const float2 f00 = __ldg(g + ix0 * GS + iy0);
        const float2 f10 = __ldg(g + ix1 * GS + iy0);
        const float2 f01 = __ldg(g + ix0 * GS + iy1);
        const float2 f11 = __ldg(g + ix1 * GS + iy1);
        const float owx = 1.0f - wx, owy = 1.0f - wy;
        const float ax = f00.x * owx + f10.x * wx;
        const float ay = f00.y * owx + f10.y * wx;
        const float bx = f01.x * owx + f11.x * wx;
        const float by = f01.y * owx + f11.y * wx;
        f[2 * i + 0] = ax * owy + bx * wy;
        f[2 * i + 1] = ay * owy + by * wy;
    }
}

__global__ void reset_kernel() { g_tile_ctr = 0; }

// one GEMM macro-step: acc[4][4] over 8 cols (j0 warp-uniform), 4 k-values
#define GEMM_KB(SMW, SMACT, PAD)                                              \
    do {                                                                      \
        float4 av[4];                                                         \
        _Pragma("unroll")                                                     \
        for (int i = 0; i < 4; i++)                                           \
            av[i] = *reinterpret_cast<const float4*>(                         \
                sm + (SMACT) + (lane + 32 * i) * (PAD) + kb * 4);             \
        _Pragma("unroll")                                                     \
        for (int kk = 0; kk < 4; kk++) {                                      \
            const float* wrow = sm + (SMW) + (kb * 4 + kk) * 128 + j0;        \
            const ulonglong2 wa = *reinterpret_cast<const ulonglong2*>(wrow);     \
            const ulonglong2 wb = *reinterpret_cast<const ulonglong2*>(wrow + 4); \
            _Pragma("unroll")                                                 \
            for (int i = 0; i < 4; i++) {                                     \
                const float* af = reinterpret_cast<const float*>(&av[i]);     \
                const u64 a = pack2(af[kk]);                                  \
                acc[i][0] = ffma2(a, wa.x, acc[i][0]);                        \
                acc[i][1] = ffma2(a, wa.y, acc[i][1]);                        \
                acc[i][2] = ffma2(a, wb.x, acc[i][2]);                        \
                acc[i][3] = ffma2(a, wb.y, acc[i][3]);                        \
            }                                                                 \
        }                                                                     \
    } while (0)

__global__ __launch_bounds__(TPB, 1)
void Model_61065845014888_kernel(
    const float* __restrict__ x,
    const float* __restrict__ grids,
    const float* __restrict__ W1, const float* __restrict__ b1,
    const float* __restrict__ W2, const float* __restrict__ b2,
    const float* __restrict__ W3, const float* __restrict__ b3,
    float* __restrict__ out)
{
    extern __shared__ float sm[];
    const int tid = threadIdx.x;

    // ---- stage weights once ----
    {
        const float4* s4 = reinterpret_cast<const float4*>(W1);
        float4*       d4 = reinterpret_cast<float4*>(sm + SM_W1);
        #pragma unroll 2
        for (int i = tid; i < 1024; i += TPB) d4[i] = s4[i];
    }
    {
        const float4* s4 = reinterpret_cast<const float4*>(W2);
        float4*       d4 = reinterpret_cast<float4*>(sm + SM_W2);
        #pragma unroll 4
        for (int i = tid; i < 4096; i += TPB) d4[i] = s4[i];
    }
    if (tid < 128) {
        sm[SM_B1 + tid] = b1[tid];
        sm[SM_B2 + tid] = b2[tid];
        sm[SM_W3 + tid] = W3[tid];
    }
    if (tid == 0) sm[SM_B3] = b3[0];

    const int wid  = tid >> 5;        // warp 0..15 -> 8-col chunk
    const int lane = tid & 31;        // point base
    const int j0   = wid * 8;

    // gather role: 4 threads per point, 4 levels each
    const int gpt = tid >> 2;         // 0..127
    const int gq  = tid & 3;          // level quarter

    __syncthreads();

    for (;;) {
        if (tid == 0)
            reinterpret_cast<int*>(sm)[SM_TILE] = atomicAdd(&g_tile_ctr, 1);
        __syncthreads();
        const int tile = reinterpret_cast<int*>(sm)[SM_TILE];
        if (tile >= NTILES) break;

        // ================= gather -> feat[pt][36] =================
        {
            const int p = tile * 128 + gpt;
            const float2 xy = __ldg(reinterpret_cast<const float2*>(x) + p);
            float f[8];
            switch (gq) {
                case 0: gather4<0>(xy, grids, f);  break;
                case 1: gather4<4>(xy, grids, f);  break;
                case 2: gather4<8>(xy, grids, f);  break;
                default: gather4<12>(xy, grids, f); break;
            }
            float4* dst = reinterpret_cast<float4*>(sm + SM_FEAT + gpt * 36 + gq * 8);
            dst[0] = make_float4(f[0], f[1], f[2], f[3]);
            dst[1] = make_float4(f[4], f[5], f[6], f[7]);
        }
        __syncthreads();

        u64 acc[4][4];

        // ================= GEMM1: h1 = relu(feat @ W1 + b1) =================
        {
            const float* brow = sm + SM_B1 + j0;
            const ulonglong2 ba = *reinterpret_cast<const ulonglong2*>(brow);
            const ulonglong2 bb = *reinterpret_cast<const ulonglong2*>(brow + 4);
            #pragma unroll
            for (int i = 0; i < 4; i++) {
                acc[i][0] = ba.x; acc[i][1] = ba.y;
                acc[i][2] = bb.x; acc[i][3] = bb.y;
            }
            #pragma unroll 1
            for (int kb = 0; kb < 8; kb++) GEMM_KB(SM_W1, SM_FEAT, 36);
        }
        // relu + store h1[pt][132]
        #pragma unroll
        for (int i = 0; i < 4; i++) {
            const int p = lane + 32 * i;
            float v[8];
            #pragma unroll
            for (int c = 0; c < 4; c++) unpack2(acc[i][c], v[2*c], v[2*c+1]);
            #pragma unroll
            for (int q = 0; q < 8; q++) v[q] = fmaxf(v[q], 0.0f);
            float4* dst = reinterpret_cast<float4*>(sm + SM_H1 + p * 132 + j0);
            dst[0] = make_float4(v[0], v[1], v[2], v[3]);
            dst[1] = make_float4(v[4], v[5], v[6], v[7]);
        }
        __syncthreads();

        // ================= GEMM2: h2 = relu(h1 @ W2 + b2) =================
        {
            const float* brow = sm + SM_B2 + j0;
            const ulonglong2 ba = *reinterpret_cast<const ulonglong2*>(brow);
            const ulonglong2 bb = *reinterpret_cast<const ulonglong2*>(brow + 4);
            #pragma unroll
            for (int i = 0; i < 4; i++) {
                acc[i][0] = ba.x; acc[i][1] = ba.y;
                acc[i][2] = bb.x; acc[i][3] = bb.y;
            }
            #pragma unroll 1
            for (int kb = 0; kb < 32; kb++) GEMM_KB(SM_W2, SM_H1, 132);
        }
        // relu + layer-3 partial dot over this warp's 8 cols
        #pragma unroll
        for (int i = 0; i < 4; i++) {
            float s = 0.0f;
            #pragma unroll
            for (int c = 0; c < 4; c++) {
                float lo, hi; unpack2(acc[i][c], lo, hi);
                s = fmaf(fmaxf(lo, 0.0f), sm[SM_W3 + j0 + 2*c],     s);
                s = fmaf(fmaxf(hi, 0.0f), sm[SM_W3 + j0 + 2*c + 1], s);
            }
            sm[SM_PART + (lane + 32 * i) * 17 + wid] = s;
        }
        __syncthreads();

        // ================= reduce 16 warp-partials per point =================
        if (tid < 128) {
            const float* pr = sm + SM_PART + tid * 17;
            float s = sm[SM_B3];
            #pragma unroll
            for (int c = 0; c < 16; c++) s += pr[c];
            out[tile * 128 + tid] = s;
        }
        __syncthreads();
    }
}

extern "C" void kernel_launch(void* const* d_in, const int* in_sizes, int n_in,
                              void* d_out, int out_size)
{
    const float* x     = (const float*)d_in[0];
    const float* grids = (const float*)d_in[1];
    const float* W1    = (const float*)d_in[2];
    const float* b1    = (const float*)d_in[3];
    const float* W2    = (const float*)d_in[4];
    const float* b2    = (const float*)d_in[5];
    const float* W3    = (const float*)d_in[6];
    const float* b3    = (const float*)d_in[7];
    float* out = (float*)d_out;
    (void)in_sizes; (void)n_in; (void)out_size;

    cudaFuncSetAttribute(Model_61065845014888_kernel,
                         cudaFuncAttributeMaxDynamicSharedMemorySize, SMEM_BYTES);

    reset_kernel<<<1, 1>>>();
    Model_61065845014888_kernel<<<NCTA, TPB, SMEM_BYTES>>>(
        x, grids, W1, b1, W2, b2, W3, b3, out);
}

// round 6
// speedup vs baseline: 1.6089x; 1.0884x over previous
#include <cuda_runtime.h>
#include <cstdint>

// ---------------------------------------------------------------------------
// Instant-NGP MLP via legacy mma.sync m16n8k8 TF32 (HMMA fallback on sm_103),
// split-tf32 operands (AhBh + AlBh + AhBl) for fp32-level accuracy.
// Persistent CTAs, 512 threads, tile = 128 points.
// Warp = 16-row group x 64-col half; weights staged in fragment-major SMEM.
// ---------------------------------------------------------------------------

#define NPTS    2097152
#define NTILES  (NPTS / 128)     // 16384
#define TPB     512
#define NCTA    148
#define GS      513

// SMEM layout in floats
#define SM_W1F  0                 // frag-major W1: 4*16*32*2   = 4096
#define SM_W2F  4096              // frag-major W2: 16*16*32*2  = 16384
#define SM_FEAT 20480             // 128*36  = 4608  (pad 36 ≡ 4 mod 32)
#define SM_H1   25088             // 128*132 = 16896 (pad 132 ≡ 4 mod 32)
#define SM_B1   41984             // 128
#define SM_B2   42112             // 128
#define SM_W3   42240             // 128
#define SM_B3   42368             // 1 (+7 pad)
#define SM_PART 42376             // 128*2 = 256
#define SM_TILE 42632             // int slot
#define SM_FLOATS 42636
#define SMEM_BYTES (SM_FLOATS * 4)   // ~170.5 KB

__device__ int g_tile_ctr;

__device__ const int kResTab[16] = {16, 20, 25, 32, 40, 50, 64, 80,
                                    101, 128, 161, 203, 256, 322, 406, 512};

__device__ __forceinline__ uint32_t tf32_rna(float f) {
    uint32_t r;
    asm("cvt.rna.tf32.f32 %0, %1;" : "=r"(r) : "f"(f));
    return r;
}

// D += A(tf32) * B(tf32), m16n8k8
__device__ __forceinline__ void mma8(float* d, const uint32_t* a,
                                     uint32_t b0, uint32_t b1) {
    asm volatile(
        "mma.sync.aligned.m16n8k8.row.col.f32.tf32.tf32.f32 "
        "{%0,%1,%2,%3}, {%4,%5,%6,%7}, {%8,%9}, {%0,%1,%2,%3};"
        : "+f"(d[0]), "+f"(d[1]), "+f"(d[2]), "+f"(d[3])
        : "r"(a[0]), "r"(a[1]), "r"(a[2]), "r"(a[3]), "r"(b0), "r"(b1));
}

template <int L0>
__device__ __forceinline__ void gather4(float2 xy, const float* __restrict__ grids,
                                        float* f) {
    #pragma unroll
    for (int i = 0; i < 4; i++) {
        const int   ri = kResTab[L0 + i];
        const float rf = (float)ri;
        const float fx = xy.x * rf, fy = xy.y * rf;
        const float fxf = floorf(fx), fyf = floorf(fy);
        const float wx = fx - fxf, wy = fy - fyf;
        int ix0 = min(max((int)fxf, 0), ri);
        int iy0 = min(max((int)fyf, 0), ri);
        int ix1 = min(ix0 + 1, ri);
        int iy1 = min(iy0 + 1, ri);
        const float2* g = reinterpret_cast<const float2*>(grids)
                        + (size_t)(L0 + i) * (GS * GS);
        const float2 f00 = __ldg(g + ix0 * GS + iy0);
        const float2 f10 = __ldg(g + ix1 * GS + iy0);
        const float2 f01 = __ldg(g + ix0 * GS + iy1);
        const float2 f11 = __ldg(g + ix1 * GS + iy1);
        const float owx = 1.0f - wx, owy = 1.0f - wy;
        const float ax = f00.x * owx + f10.x * wx;
        const float ay = f00.y * owx + f10.y * wx;
        const float bx = f01.x * owx + f11.x * wx;
        const float by = f01.y * owx + f11.y * wx;
        f[2 * i + 0] = ax * owy + bx * wy;
        f[2 * i + 1] = ay * owy + by * wy;
    }
}

__global__ void reset_kernel() { g_tile_ctr = 0; }

// one GEMM k-step: load A frag (fp32) + split, then 8 n-frags split-B, 3 mma each
#define MMA_KSTEP(SMACT, PAD, SMWF)                                           \
    do {                                                                      \
        const int acol = s * 8 + tg;                                          \
        float a0 = sm[(SMACT) + (arow)     * (PAD) + acol];                   \
        float a1 = sm[(SMACT) + (arow + 8) * (PAD) + acol];                   \
        float a2 = sm[(SMACT) + (arow)     * (PAD) + acol + 4];               \
        float a3 = sm[(SMACT) + (arow + 8) * (PAD) + acol + 4];               \
        uint32_t ah[4], al[4];                                                \
        ah[0] = tf32_rna(a0); al[0] = __float_as_uint(a0 - __uint_as_float(ah[0])); \
        ah[1] = tf32_rna(a1); al[1] = __float_as_uint(a1 - __uint_as_float(ah[1])); \
        ah[2] = tf32_rna(a2); al[2] = __float_as_uint(a2 - __uint_as_float(ah[2])); \
        ah[3] = tf32_rna(a3); al[3] = __float_as_uint(a3 - __uint_as_float(ah[3])); \
        _Pragma("unroll")                                                     \
        for (int f = 0; f < 8; f++) {                                         \
            const int g = ch * 8 + f;                                         \
            const float2 w = *reinterpret_cast<const float2*>(                \
                sm + (SMWF) + (((s * 16 + g) * 32 + lane) << 1));             \
            uint32_t bh0 = tf32_rna(w.x), bh1 = tf32_rna(w.y);                \
            uint32_t bl0 = __float_as_uint(w.x - __uint_as_float(bh0));       \
            uint32_t bl1 = __float_as_uint(w.y - __uint_as_float(bh1));       \
            mma8(d[f], ah, bh0, bh1);                                         \
            mma8(d[f], al, bh0, bh1);                                         \
            mma8(d[f], ah, bl0, bl1);                                         \
        }                                                                     \
    } while (0)

__global__ __launch_bounds__(TPB, 1)
void Model_61065845014888_kernel(
    const float* __restrict__ x,
    const float* __restrict__ grids,
    const float* __restrict__ W1, const float* __restrict__ b1,
    const float* __restrict__ W2, const float* __restrict__ b2,
    const float* __restrict__ W3, const float* __restrict__ b3,
    float* __restrict__ out)
{
    extern __shared__ float sm[];
    const int tid = threadIdx.x;

    // ---- stage weights into fragment-major layout (once) ----
    // W1F[i]: i = (((s*16 + g)*32 + lane)*2 + r)
    //   value = W1[s*8 + (lane&3) + 4r][g*8 + (lane>>2)]
    for (int i = tid; i < 4096; i += TPB) {
        int r = i & 1, ln = (i >> 1) & 31, g = (i >> 6) & 15, s = i >> 10;
        int k = s * 8 + (ln & 3) + 4 * r;
        int j = g * 8 + (ln >> 2);
        sm[SM_W1F + i] = W1[k * 128 + j];
    }
    for (int i = tid; i < 16384; i += TPB) {
        int r = i & 1, ln = (i >> 1) & 31, g = (i >> 6) & 15, s = i >> 10;
        int k = s * 8 + (ln & 3) + 4 * r;
        int j = g * 8 + (ln >> 2);
        sm[SM_W2F + i] = W2[k * 128 + j];
    }
    if (tid < 128) {
        sm[SM_B1 + tid] = b1[tid];
        sm[SM_B2 + tid] = b2[tid];
        sm[SM_W3 + tid] = W3[tid];
    }
    if (tid == 0) sm[SM_B3] = b3[0];

    const int wid  = tid >> 5;
    const int lane = tid & 31;
    const int rg   = wid & 7;         // 16-row group
    const int ch   = wid >> 3;        // 64-col half
    const int tg   = lane & 3;        // thread-in-group (k / col-pair idx)
    const int gid  = lane >> 2;       // group id (row idx)
    const int arow = rg * 16 + gid;
    const int jw   = ch * 64;         // warp col base

    // gather role: 4 threads per point, 4 levels each
    const int gpt = tid >> 2;
    const int gq  = tid & 3;

    __syncthreads();

    for (;;) {
        if (tid == 0)
            reinterpret_cast<int*>(sm)[SM_TILE] = atomicAdd(&g_tile_ctr, 1);
        __syncthreads();
        const int tile = reinterpret_cast<int*>(sm)[SM_TILE];
        if (tile >= NTILES) break;

        // ================= gather -> feat[pt][36] (fp32) =================
        {
            const int p = tile * 128 + gpt;
            const float2 xy = __ldg(reinterpret_cast<const float2*>(x) + p);
            float f[8];
            switch (gq) {
                case 0: gather4<0>(xy, grids, f);  break;
                case 1: gather4<4>(xy, grids, f);  break;
                case 2: gather4<8>(xy, grids, f);  break;
                default: gather4<12>(xy, grids, f); break;
            }
            float4* dst = reinterpret_cast<float4*>(sm + SM_FEAT + gpt * 36 + gq * 8);
            dst[0] = make_float4(f[0], f[1], f[2], f[3]);
            dst[1] = make_float4(f[4], f[5], f[6], f[7]);
        }
        __syncthreads();

        float d[8][4];

        // ================= GEMM1: D1 = feat @ W1 + b1 =================
        #pragma unroll
        for (int f = 0; f < 8; f++) {
            const float2 bv = *reinterpret_cast<const float2*>(
                sm + SM_B1 + jw + f * 8 + tg * 2);
            d[f][0] = bv.x; d[f][1] = bv.y;
            d[f][2] = bv.x; d[f][3] = bv.y;
        }
        #pragma unroll 1
        for (int s = 0; s < 4; s++) MMA_KSTEP(SM_FEAT, 36, SM_W1F);

        // relu + store h1 (fp32)
        #pragma unroll
        for (int f = 0; f < 8; f++) {
            const int jc = jw + f * 8 + tg * 2;
            *reinterpret_cast<float2*>(sm + SM_H1 + arow * 132 + jc) =
                make_float2(fmaxf(d[f][0], 0.0f), fmaxf(d[f][1], 0.0f));
            *reinterpret_cast<float2*>(sm + SM_H1 + (arow + 8) * 132 + jc) =
                make_float2(fmaxf(d[f][2], 0.0f), fmaxf(d[f][3], 0.0f));
        }
        __syncthreads();

        // ================= GEMM2: D2 = h1 @ W2 + b2 =================
        #pragma unroll
        for (int f = 0; f < 8; f++) {
            const float2 bv = *reinterpret_cast<const float2*>(
                sm + SM_B2 + jw + f * 8 + tg * 2);
            d[f][0] = bv.x; d[f][1] = bv.y;
            d[f][2] = bv.x; d[f][3] = bv.y;
        }
        #pragma unroll 1
        for (int s = 0; s < 16; s++) MMA_KSTEP(SM_H1, 132, SM_W2F);

        // ================= epilogue: relu + W3 dot + reduce =================
        {
            float slo = 0.0f, shi = 0.0f;
            #pragma unroll
            for (int f = 0; f < 8; f++) {
                const int jc = jw + f * 8 + tg * 2;
                const float w3a = sm[SM_W3 + jc];
                const float w3b = sm[SM_W3 + jc + 1];
                slo = fmaf(fmaxf(d[f][0], 0.0f), w3a, slo);
                slo = fmaf(fmaxf(d[f][1], 0.0f), w3b, slo);
                shi = fmaf(fmaxf(d[f][2], 0.0f), w3a, shi);
                shi = fmaf(fmaxf(d[f][3], 0.0f), w3b, shi);
            }
            // reduce over the 4 lanes sharing a row (lane%4)
            slo += __shfl_xor_sync(0xFFFFFFFF, slo, 1);
            slo += __shfl_xor_sync(0xFFFFFFFF, slo, 2);
            shi += __shfl_xor_sync(0xFFFFFFFF, shi, 1);
            shi += __shfl_xor_sync(0xFFFFFFFF, shi, 2);
            if (tg == 0) {
                sm[SM_PART + arow * 2 + ch]       = slo;
                sm[SM_PART + (arow + 8) * 2 + ch] = shi;
            }
        }
        __syncthreads();

        if (tid < 128)
            out[tile * 128 + tid] = sm[SM_PART + tid * 2]
                                  + sm[SM_PART + tid * 2 + 1]
                                  + sm[SM_B3];
        __syncthreads();
    }
}

extern "C" void kernel_launch(void* const* d_in, const int* in_sizes, int n_in,
                              void* d_out, int out_size)
{
    const float* x     = (const float*)d_in[0];
    const float* grids = (const float*)d_in[1];
    const float* W1    = (const float*)d_in[2];
    const float* b1    = (const float*)d_in[3];
    const float* W2    = (const float*)d_in[4];
    const float* b2    = (const float*)d_in[5];
    const float* W3    = (const float*)d_in[6];
    const float* b3    = (const float*)d_in[7];
    float* out = (float*)d_out;
    (void)in_sizes; (void)n_in; (void)out_size;

    cudaFuncSetAttribute(Model_61065845014888_kernel,
                         cudaFuncAttributeMaxDynamicSharedMemorySize, SMEM_BYTES);

    reset_kernel<<<1, 1>>>();
    Model_61065845014888_kernel<<<NCTA, TPB, SMEM_BYTES>>>(
        x, grids, W1, b1, W2, b2, W3, b3, out);
}

// round 7
// speedup vs baseline: 1.6878x; 1.0490x over previous
#include <cuda_runtime.h>
#include <cstdint>

// ---------------------------------------------------------------------------
// Instant-NGP MLP via legacy mma.sync m16n8k8 TF32 (HMMA fallback on sm_103),
// split-tf32 (AhBh + AlBh + AhBl). W2 operand splits PRECOMPUTED into SMEM
// (one-time) -> per-tile ALU work collapses. FEAT aliases H1 region.
// ---------------------------------------------------------------------------

#define NPTS    2097152
#define NTILES  (NPTS / 128)     // 16384
#define TPB     512
#define NCTA    148
#define GS      513

// SMEM layout in floats
#define SM_W1F   0                // frag-major W1 master: 4096
#define SM_W2FH  4096             // frag-major W2 hi (tf32 bits): 16384
#define SM_W2FL  20480            // frag-major W2 lo (tf32 bits): 16384
#define SM_UNION 36864            // H1: 128*132 = 16896 ; FEAT aliases front
#define SM_FEAT  SM_UNION         //   FEAT: 128*36 = 4608
#define SM_H1    SM_UNION
#define SM_B1    53760            // 128
#define SM_B2    53888            // 128
#define SM_W3    54016            // 128
#define SM_B3    54144            // 4
#define SM_PART  54148            // 256
#define SM_TILE  54404            // int slot
#define SM_FLOATS 54408
#define SMEM_BYTES (SM_FLOATS * 4)   // 217632 B

__device__ int g_tile_ctr;

__device__ const int kResTab[16] = {16, 20, 25, 32, 40, 50, 64, 80,
                                    101, 128, 161, 203, 256, 322, 406, 512};

__device__ __forceinline__ uint32_t tf32_rna(float f) {
    uint32_t r;
    asm("cvt.rna.tf32.f32 %0, %1;" : "=r"(r) : "f"(f));
    return r;
}
// truncate-split: hi = bits & 0xFFFFE000 (exact fp32), lo = a - hi (exact)
__device__ __forceinline__ void split_trunc(float a, uint32_t& hi, uint32_t& lo) {
    hi = __float_as_uint(a) & 0xFFFFE000u;
    lo = __float_as_uint(a - __uint_as_float(hi));
}

// D += A(tf32) * B(tf32), m16n8k8
__device__ __forceinline__ void mma8(float* d, const uint32_t* a,
                                     uint32_t b0, uint32_t b1) {
    asm volatile(
        "mma.sync.aligned.m16n8k8.row.col.f32.tf32.tf32.f32 "
        "{%0,%1,%2,%3}, {%4,%5,%6,%7}, {%8,%9}, {%0,%1,%2,%3};"
        : "+f"(d[0]), "+f"(d[1]), "+f"(d[2]), "+f"(d[3])
        : "r"(a[0]), "r"(a[1]), "r"(a[2]), "r"(a[3]), "r"(b0), "r"(b1));
}

template <int L0>
__device__ __forceinline__ void gather4(float2 xy, const float* __restrict__ grids,
                                        float* f) {
    #pragma unroll
    for (int i = 0; i < 4; i++) {
        const int   ri = kResTab[L0 + i];
        const float rf = (float)ri;
        const float fx = xy.x * rf, fy = xy.y * rf;
        const float fxf = floorf(fx), fyf = floorf(fy);
        const float wx = fx - fxf, wy = fy - fyf;
        int ix0 = min(max((int)fxf, 0), ri);
        int iy0 = min(max((int)fyf, 0), ri);
        int ix1 = min(ix0 + 1, ri);
        int iy1 = min(iy0 + 1, ri);
        const float2* g = reinterpret_cast<const float2*>(grids)
                        + (size_t)(L0 + i) * (GS * GS);
        const float2 f00 = __ldg(g + ix0 * GS + iy0);
        const float2 f10 = __ldg(g + ix1 * GS + iy0);
        const float2 f01 = __ldg(g + ix0 * GS + iy1);
        const float2 f11 = __ldg(g + ix1 * GS + iy1);
        const float owx = 1.0f - wx, owy = 1.0f - wy;
        const float ax = f00.x * owx + f10.x * wx;
        const float ay = f00.y * owx + f10.y * wx;
        const float bx = f01.x * owx + f11.x * wx;
        const float by = f01.y * owx + f11.y * wx;
        f[2 * i + 0] = ax * owy + bx * wy;
        f[2 * i + 1] = ay * owy + by * wy;
    }
}

__global__ void reset_kernel() { g_tile_ctr = 0; }

// load + split A frag (4 regs hi, 4 lo) from activation SMEM
#define LOAD_A_SPLIT(SMACT, PAD)                                              \
    uint32_t ah[4], al[4];                                                    \
    do {                                                                      \
        const int acol = s * 8 + tg;                                          \
        split_trunc(sm[(SMACT) + (arow)     * (PAD) + acol],     ah[0], al[0]); \
        split_trunc(sm[(SMACT) + (arow + 8) * (PAD) + acol],     ah[1], al[1]); \
        split_trunc(sm[(SMACT) + (arow)     * (PAD) + acol + 4], ah[2], al[2]); \
        split_trunc(sm[(SMACT) + (arow + 8) * (PAD) + acol + 4], ah[3], al[3]); \
    } while (0)

__global__ __launch_bounds__(TPB, 1)
void Model_61065845014888_kernel(
    const float* __restrict__ x,
    const float* __restrict__ grids,
    const float* __restrict__ W1, const float* __restrict__ b1,
    const float* __restrict__ W2, const float* __restrict__ b2,
    const float* __restrict__ W3, const float* __restrict__ b3,
    float* __restrict__ out)
{
    extern __shared__ float sm[];
    const int tid = threadIdx.x;

    // ---- stage W1 master, frag-major ----
    for (int i = tid; i < 4096; i += TPB) {
        int r = i & 1, ln = (i >> 1) & 31, g = (i >> 6) & 15, s = i >> 10;
        int k = s * 8 + (ln & 3) + 4 * r;
        int j = g * 8 + (ln >> 2);
        sm[SM_W1F + i] = W1[k * 128 + j];
    }
    // ---- stage W2 pre-split (hi/lo tf32 bits), frag-major ----
    for (int i = tid; i < 16384; i += TPB) {
        int r = i & 1, ln = (i >> 1) & 31, g = (i >> 6) & 15, s = i >> 10;
        int k = s * 8 + (ln & 3) + 4 * r;
        int j = g * 8 + (ln >> 2);
        float w = W2[k * 128 + j];
        uint32_t hb = tf32_rna(w);
        float lo = w - __uint_as_float(hb);
        uint32_t lb = tf32_rna(lo);
        sm[SM_W2FH + i] = __uint_as_float(hb);
        sm[SM_W2FL + i] = __uint_as_float(lb);
    }
    if (tid < 128) {
        sm[SM_B1 + tid] = b1[tid];
        sm[SM_B2 + tid] = b2[tid];
        sm[SM_W3 + tid] = W3[tid];
    }
    if (tid == 0) sm[SM_B3] = b3[0];

    const int wid  = tid >> 5;
    const int lane = tid & 31;
    const int rg   = wid & 7;         // 16-row group
    const int ch   = wid >> 3;        // 64-col half
    const int tg   = lane & 3;
    const int gid  = lane >> 2;
    const int arow = rg * 16 + gid;
    const int jw   = ch * 64;

    const int gpt = tid >> 2;
    const int gq  = tid & 3;

    __syncthreads();

    for (;;) {
        if (tid == 0)
            reinterpret_cast<int*>(sm)[SM_TILE] = atomicAdd(&g_tile_ctr, 1);
        __syncthreads();
        const int tile = reinterpret_cast<int*>(sm)[SM_TILE];
        if (tile >= NTILES) break;

        // ================= gather -> feat[pt][36] (aliases H1 region) ======
        {
            const int p = tile * 128 + gpt;
            const float2 xy = __ldg(reinterpret_cast<const float2*>(x) + p);
            float f[8];
            switch (gq) {
                case 0: gather4<0>(xy, grids, f);  break;
                case 1: gather4<4>(xy, grids, f);  break;
                case 2: gather4<8>(xy, grids, f);  break;
                default: gather4<12>(xy, grids, f); break;
            }
            float4* dst = reinterpret_cast<float4*>(sm + SM_FEAT + gpt * 36 + gq * 8);
            dst[0] = make_float4(f[0], f[1], f[2], f[3]);
            dst[1] = make_float4(f[4], f[5], f[6], f[7]);
        }
        __syncthreads();

        float d[8][4];

        // ================= GEMM1: D1 = feat @ W1 + b1 (on-the-fly B split) =
        #pragma unroll
        for (int f = 0; f < 8; f++) {
            const float2 bv = *reinterpret_cast<const float2*>(
                sm + SM_B1 + jw + f * 8 + tg * 2);
            d[f][0] = bv.x; d[f][1] = bv.y;
            d[f][2] = bv.x; d[f][3] = bv.y;
        }
        #pragma unroll 1
        for (int s = 0; s < 4; s++) {
            LOAD_A_SPLIT(SM_FEAT, 36);
            #pragma unroll
            for (int f = 0; f < 8; f++) {
                const int g = ch * 8 + f;
                const float2 w = *reinterpret_cast<const float2*>(
                    sm + SM_W1F + (((s * 16 + g) * 32 + lane) << 1));
                uint32_t bh0, bl0, bh1, bl1;
                split_trunc(w.x, bh0, bl0);
                split_trunc(w.y, bh1, bl1);
                mma8(d[f], ah, bh0, bh1);
                mma8(d[f], al, bh0, bh1);
                mma8(d[f], ah, bl0, bl1);
            }
        }

        // FEAT reads complete everywhere before h1 overwrites the region
        __syncthreads();

        // relu + store h1 (fp32)
        #pragma unroll
        for (int f = 0; f < 8; f++) {
            const int jc = jw + f * 8 + tg * 2;
            *reinterpret_cast<float2*>(sm + SM_H1 + arow * 132 + jc) =
                make_float2(fmaxf(d[f][0], 0.0f), fmaxf(d[f][1], 0.0f));
            *reinterpret_cast<float2*>(sm + SM_H1 + (arow + 8) * 132 + jc) =
                make_float2(fmaxf(d[f][2], 0.0f), fmaxf(d[f][3], 0.0f));
        }
        __syncthreads();

        // ================= GEMM2: D2 = h1 @ W2 + b2 (pre-split B) ==========
        #pragma unroll
        for (int f = 0; f < 8; f++) {
            const float2 bv = *reinterpret_cast<const float2*>(
                sm + SM_B2 + jw + f * 8 + tg * 2);
            d[f][0] = bv.x; d[f][1] = bv.y;
            d[f][2] = bv.x; d[f][3] = bv.y;
        }
        #pragma unroll 1
        for (int s = 0; s < 16; s++) {
            LOAD_A_SPLIT(SM_H1, 132);
            const int fb = ((s * 16 + ch * 8) * 32 + lane) << 1;
            #pragma unroll
            for (int f = 0; f < 8; f++) {
                const uint2 wh = *reinterpret_cast<const uint2*>(
                    sm + SM_W2FH + fb + (f << 6));
                const uint2 wl = *reinterpret_cast<const uint2*>(
                    sm + SM_W2FL + fb + (f << 6));
                mma8(d[f], ah, wh.x, wh.y);
                mma8(d[f], al, wh.x, wh.y);
                mma8(d[f], ah, wl.x, wl.y);
            }
        }

        // ================= epilogue: relu + W3 dot + reduce =================
        {
            float slo = 0.0f, shi = 0.0f;
            #pragma unroll
            for (int f = 0; f < 8; f++) {
                const int jc = jw + f * 8 + tg * 2;
                const float w3a = sm[SM_W3 + jc];
                const float w3b = sm[SM_W3 + jc + 1];
                slo = fmaf(fmaxf(d[f][0], 0.0f), w3a, slo);
                slo = fmaf(fmaxf(d[f][1], 0.0f), w3b, slo);
                shi = fmaf(fmaxf(d[f][2], 0.0f), w3a, shi);
                shi = fmaf(fmaxf(d[f][3], 0.0f), w3b, shi);
            }
            slo += __shfl_xor_sync(0xFFFFFFFF, slo, 1);
            slo += __shfl_xor_sync(0xFFFFFFFF, slo, 2);
            shi += __shfl_xor_sync(0xFFFFFFFF, shi, 1);
            shi += __shfl_xor_sync(0xFFFFFFFF, shi, 2);
            if (tg == 0) {
                sm[SM_PART + arow * 2 + ch]       = slo;
                sm[SM_PART + (arow + 8) * 2 + ch] = shi;
            }
        }
        __syncthreads();

        if (tid < 128)
            out[tile * 128 + tid] = sm[SM_PART + tid * 2]
                                  + sm[SM_PART + tid * 2 + 1]
                                  + sm[SM_B3];
        __syncthreads();
    }
}

extern "C" void kernel_launch(void* const* d_in, const int* in_sizes, int n_in,
                              void* d_out, int out_size)
{
    const float* x     = (const float*)d_in[0];
    const float* grids = (const float*)d_in[1];
    const float* W1    = (const float*)d_in[2];
    const float* b1    = (const float*)d_in[3];
    const float* W2    = (const float*)d_in[4];
    const float* b2    = (const float*)d_in[5];
    const float* W3    = (const float*)d_in[6];
    const float* b3    = (const float*)d_in[7];
    float* out = (float*)d_out;
    (void)in_sizes; (void)n_in; (void)out_size;

    cudaFuncSetAttribute(Model_61065845014888_kernel,
                         cudaFuncAttributeMaxDynamicSharedMemorySize, SMEM_BYTES);

    reset_kernel<<<1, 1>>>();
    Model_61065845014888_kernel<<<NCTA, TPB, SMEM_BYTES>>>(
        x, grids, W1, b1, W2, b2, W3, b3, out);
}

// round 8
// speedup vs baseline: 2.7843x; 1.6496x over previous
#include <cuda_runtime.h>
#include <cuda_bf16.h>
#include <cstdint>

// ---------------------------------------------------------------------------
// Instant-NGP MLP via legacy mma.sync m16n8k16 BF16 (HMMA fallback on sm_103),
// split-bf16 operands (AhBh + AlBh + AhBl), everything pre-split:
//   weights staged once as packed bf16x2 hi/lo fragments,
//   activations written split by gather / GEMM1 epilogue.
// MMA inner loops: LDS + HMMA only.
// ---------------------------------------------------------------------------

#define NPTS    2097152
#define NTILES  (NPTS / 128)     // 16384
#define TPB     512
#define NCTA    148
#define GS      513

// SMEM map in u32 units (bit-packed bf16x2 planes), float regions at end
#define U_W1FH  0                 // 2*16*32*2 = 2048
#define U_W1FL  2048
#define U_W2FH  4096              // 8*16*32*2 = 8192
#define U_W2FL  12288
#define U_FEATH 20480             // 128*20 = 2560
#define U_FEATL 23040
#define U_H1H   25600             // 128*68 = 8704
#define U_H1L   34304
#define F_B1    43008             // float[128]
#define F_B2    43136
#define F_W3    43264
#define F_B3    43392             // float[4]
#define F_PART  43396             // float[256]
#define I_TILE  43652
#define SM_U32  43656
#define SMEM_BYTES (SM_U32 * 4)   // 174624 B

__device__ int g_tile_ctr;

__device__ const int kResTab[16] = {16, 20, 25, 32, 40, 50, 64, 80,
                                    101, 128, 161, 203, 256, 322, 406, 512};

__device__ __forceinline__ float bf16f(float v) {
    return __bfloat162float(__float2bfloat16_rn(v));
}
// pack two floats to bf16x2 (e0 -> low 16 bits, e1 -> high)
__device__ __forceinline__ uint32_t packbf(float e0, float e1) {
    __nv_bfloat162 t = __halves2bfloat162(__float2bfloat16_rn(e0),
                                          __float2bfloat16_rn(e1));
    return *reinterpret_cast<uint32_t*>(&t);
}

// D += A(bf16) * B(bf16), m16n8k16
__device__ __forceinline__ void mmab(float* d, const uint32_t* a,
                                     uint32_t b0, uint32_t b1) {
    asm volatile(
        "mma.sync.aligned.m16n8k16.row.col.f32.bf16.bf16.f32 "
        "{%0,%1,%2,%3}, {%4,%5,%6,%7}, {%8,%9}, {%0,%1,%2,%3};"
        : "+f"(d[0]), "+f"(d[1]), "+f"(d[2]), "+f"(d[3])
        : "r"(a[0]), "r"(a[1]), "r"(a[2]), "r"(a[3]), "r"(b0), "r"(b1));
}

template <int L0>
__device__ __forceinline__ void gather4(float2 xy, const float* __restrict__ grids,
                                        float* f) {
    #pragma unroll
    for (int i = 0; i < 4; i++) {
        const int   ri = kResTab[L0 + i];
        const float rf = (float)ri;
        const float fx = xy.x * rf, fy = xy.y * rf;
        const float fxf = floorf(fx), fyf = floorf(fy);
        const float wx = fx - fxf, wy = fy - fyf;
        int ix0 = min(max((int)fxf, 0), ri);
        int iy0 = min(max((int)fyf, 0), ri);
        int ix1 = min(ix0 + 1, ri);
        int iy1 = min(iy0 + 1, ri);
        const float2* g = reinterpret_cast<const float2*>(grids)
                        + (size_t)(L0 + i) * (GS * GS);
        const float2 f00 = __ldg(g + ix0 * GS + iy0);
        const float2 f10 = __ldg(g + ix1 * GS + iy0);
        const float2 f01 = __ldg(g + ix0 * GS + iy1);
        const float2 f11 = __ldg(g + ix1 * GS + iy1);
        const float owx = 1.0f - wx, owy = 1.0f - wy;
        const float ax = f00.x * owx + f10.x * wx;
        const float ay = f00.y * owx + f10.y * wx;
        const float bx = f01.x * owx + f11.x * wx;
        const float by = f01.y * owx + f11.y * wx;
        f[2 * i + 0] = ax * owy + bx * wy;
        f[2 * i + 1] = ay * owy + by * wy;
    }
}

__global__ void reset_kernel() { g_tile_ctr = 0; }

__global__ __launch_bounds__(TPB, 1)
void Model_61065845014888_kernel(
    const float* __restrict__ x,
    const float* __restrict__ grids,
    const float* __restrict__ W1, const float* __restrict__ b1,
    const float* __restrict__ W2, const float* __restrict__ b2,
    const float* __restrict__ W3, const float* __restrict__ b3,
    float* __restrict__ out)
{
    extern __shared__ float sm[];
    uint32_t* smu = reinterpret_cast<uint32_t*>(sm);
    const int tid = threadIdx.x;

    // ---- stage W1 frags (split bf16, packed pairs), once ----
    // frag index i: r = i&1 (reg), lane = (i>>1)&31, g = (i>>6)&15, s = i>>10
    // k = s*16 + 2*(lane&3) + 8r (+0/+1 packed), j = g*8 + (lane>>2)
    for (int i = tid; i < 2048; i += TPB) {
        int r = i & 1, ln = (i >> 1) & 31, g = (i >> 6) & 15, s = i >> 10;
        int k = s * 16 + 2 * (ln & 3) + 8 * r;
        int j = g * 8 + (ln >> 2);
        float w0 = W1[k * 128 + j], w1 = W1[(k + 1) * 128 + j];
        float h0 = bf16f(w0), h1 = bf16f(w1);
        smu[U_W1FH + i] = packbf(h0, h1);
        smu[U_W1FL + i] = packbf(w0 - h0, w1 - h1);
    }
    for (int i = tid; i < 8192; i += TPB) {
        int r = i & 1, ln = (i >> 1) & 31, g = (i >> 6) & 15, s = i >> 10;
        int k = s * 16 + 2 * (ln & 3) + 8 * r;
        int j = g * 8 + (ln >> 2);
        float w0 = W2[k * 128 + j], w1 = W2[(k + 1) * 128 + j];
        float h0 = bf16f(w0), h1 = bf16f(w1);
        smu[U_W2FH + i] = packbf(h0, h1);
        smu[U_W2FL + i] = packbf(w0 - h0, w1 - h1);
    }
    if (tid < 128) {
        sm[F_B1 + tid] = b1[tid];
        sm[F_B2 + tid] = b2[tid];
        sm[F_W3 + tid] = W3[tid];
    }
    if (tid == 0) sm[F_B3] = b3[0];

    const int wid  = tid >> 5;
    const int lane = tid & 31;
    const int rg   = wid & 7;         // 16-row group
    const int ch   = wid >> 3;        // 64-col half
    const int tg   = lane & 3;
    const int gid  = lane >> 2;
    const int arow = rg * 16 + gid;
    const int jw   = ch * 64;

    const int gpt = tid >> 2;
    const int gq  = tid & 3;

    __syncthreads();

    for (;;) {
        if (tid == 0)
            reinterpret_cast<int*>(smu)[I_TILE] = atomicAdd(&g_tile_ctr, 1);
        __syncthreads();
        const int tile = reinterpret_cast<int*>(smu)[I_TILE];
        if (tile >= NTILES) break;

        // ============ gather -> split bf16 feat (stride 20 u32) ============
        {
            const int p = tile * 128 + gpt;
            const float2 xy = __ldg(reinterpret_cast<const float2*>(x) + p);
            float f[8];
            switch (gq) {
                case 0: gather4<0>(xy, grids, f);  break;
                case 1: gather4<4>(xy, grids, f);  break;
                case 2: gather4<8>(xy, grids, f);  break;
                default: gather4<12>(xy, grids, f); break;
            }
            uint32_t hi[4], lo[4];
            #pragma unroll
            for (int c = 0; c < 4; c++) {
                float h0 = bf16f(f[2*c]), h1 = bf16f(f[2*c+1]);
                hi[c] = packbf(h0, h1);
                lo[c] = packbf(f[2*c] - h0, f[2*c+1] - h1);
            }
            *reinterpret_cast<uint4*>(smu + U_FEATH + gpt * 20 + gq * 4) =
                make_uint4(hi[0], hi[1], hi[2], hi[3]);
            *reinterpret_cast<uint4*>(smu + U_FEATL + gpt * 20 + gq * 4) =
                make_uint4(lo[0], lo[1], lo[2], lo[3]);
        }
        __syncthreads();

        float d[8][4];

        // ============ GEMM1: D1 = feat @ W1 + b1 (K=32, 2 k16-steps) =======
        #pragma unroll
        for (int f = 0; f < 8; f++) {
            const float2 bv = *reinterpret_cast<const float2*>(
                sm + F_B1 + jw + f * 8 + tg * 2);
            d[f][0] = bv.x; d[f][1] = bv.y;
            d[f][2] = bv.x; d[f][3] = bv.y;
        }
        #pragma unroll
        for (int s = 0; s < 2; s++) {
            const int acol = s * 8 + tg;
            uint32_t ah[4], al[4];
            ah[0] = smu[U_FEATH + arow * 20 + acol];
            ah[1] = smu[U_FEATH + (arow + 8) * 20 + acol];
            ah[2] = smu[U_FEATH + arow * 20 + acol + 4];
            ah[3] = smu[U_FEATH + (arow + 8) * 20 + acol + 4];
            al[0] = smu[U_FEATL + arow * 20 + acol];
            al[1] = smu[U_FEATL + (arow + 8) * 20 + acol];
            al[2] = smu[U_FEATL + arow * 20 + acol + 4];
            al[3] = smu[U_FEATL + (arow + 8) * 20 + acol + 4];
            const int fb = ((s * 16 + ch * 8) * 32 + lane) * 2;
            #pragma unroll
            for (int f = 0; f < 8; f++) {
                const uint2 wh = *reinterpret_cast<const uint2*>(
                    smu + U_W1FH + fb + f * 64);
                const uint2 wl = *reinterpret_cast<const uint2*>(
                    smu + U_W1FL + fb + f * 64);
                mmab(d[f], ah, wh.x, wh.y);
                mmab(d[f], al, wh.x, wh.y);
                mmab(d[f], ah, wl.x, wl.y);
            }
        }

        // relu + split-store h1 (stride 68 u32)
        #pragma unroll
        for (int f = 0; f < 8; f++) {
            const int jc = jw / 2 + f * 4 + tg;   // u32 col
            float v0 = fmaxf(d[f][0], 0.0f), v1 = fmaxf(d[f][1], 0.0f);
            float v2 = fmaxf(d[f][2], 0.0f), v3 = fmaxf(d[f][3], 0.0f);
            float h0 = bf16f(v0), h1 = bf16f(v1), h2 = bf16f(v2), h3 = bf16f(v3);
            smu[U_H1H + arow * 68 + jc]       = packbf(h0, h1);
            smu[U_H1L + arow * 68 + jc]       = packbf(v0 - h0, v1 - h1);
            smu[U_H1H + (arow + 8) * 68 + jc] = packbf(h2, h3);
            smu[U_H1L + (arow + 8) * 68 + jc] = packbf(v2 - h2, v3 - h3);
        }
        __syncthreads();

        // ============ GEMM2: D2 = h1 @ W2 + b2 (K=128, 8 k16-steps) ========
        #pragma unroll
        for (int f = 0; f < 8; f++) {
            const float2 bv = *reinterpret_cast<const float2*>(
                sm + F_B2 + jw + f * 8 + tg * 2);
            d[f][0] = bv.x; d[f][1] = bv.y;
            d[f][2] = bv.x; d[f][3] = bv.y;
        }
        #pragma unroll 1
        for (int s = 0; s < 8; s++) {
            const int acol = s * 8 + tg;
            uint32_t ah[4], al[4];
            ah[0] = smu[U_H1H + arow * 68 + acol];
            ah[1] = smu[U_H1H + (arow + 8) * 68 + acol];
            ah[2] = smu[U_H1H + arow * 68 + acol + 4];
            ah[3] = smu[U_H1H + (arow + 8) * 68 + acol + 4];
            al[0] = smu[U_H1L + arow * 68 + acol];
            al[1] = smu[U_H1L + (arow + 8) * 68 + acol];
            al[2] = smu[U_H1L + arow * 68 + acol + 4];
            al[3] = smu[U_H1L + (arow + 8) * 68 + acol + 4];
            const int fb = ((s * 16 + ch * 8) * 32 + lane) * 2;
            #pragma unroll
            for (int f = 0; f < 8; f++) {
                const uint2 wh = *reinterpret_cast<const uint2*>(
                    smu + U_W2FH + fb + f * 64);
                const uint2 wl = *reinterpret_cast<const uint2*>(
                    smu + U_W2FL + fb + f * 64);
                mmab(d[f], ah, wh.x, wh.y);
                mmab(d[f], al, wh.x, wh.y);
                mmab(d[f], ah, wl.x, wl.y);
            }
        }

        // ============ epilogue: relu + W3 dot + reduce ============
        {
            float slo = 0.0f, shi = 0.0f;
            #pragma unroll
            for (int f = 0; f < 8; f++) {
                const int jc = jw + f * 8 + tg * 2;
                const float w3a = sm[F_W3 + jc];
                const float w3b = sm[F_W3 + jc + 1];
                slo = fmaf(fmaxf(d[f][0], 0.0f), w3a, slo);
                slo = fmaf(fmaxf(d[f][1], 0.0f), w3b, slo);
                shi = fmaf(fmaxf(d[f][2], 0.0f), w3a, shi);
                shi = fmaf(fmaxf(d[f][3], 0.0f), w3b, shi);
            }
            slo += __shfl_xor_sync(0xFFFFFFFF, slo, 1);
            slo += __shfl_xor_sync(0xFFFFFFFF, slo, 2);
            shi += __shfl_xor_sync(0xFFFFFFFF, shi, 1);
            shi += __shfl_xor_sync(0xFFFFFFFF, shi, 2);
            if (tg == 0) {
                sm[F_PART + arow * 2 + ch]       = slo;
                sm[F_PART + (arow + 8) * 2 + ch] = shi;
            }
        }
        __syncthreads();

        if (tid < 128)
            out[tile * 128 + tid] = sm[F_PART + tid * 2]
                                  + sm[F_PART + tid * 2 + 1]
                                  + sm[F_B3];
        __syncthreads();
    }
}

extern "C" void kernel_launch(void* const* d_in, const int* in_sizes, int n_in,
                              void* d_out, int out_size)
{
    const float* x     = (const float*)d_in[0];
    const float* grids = (const float*)d_in[1];
    const float* W1    = (const float*)d_in[2];
    const float* b1    = (const float*)d_in[3];
    const float* W2    = (const float*)d_in[4];
    const float* b2    = (const float*)d_in[5];
    const float* W3    = (const float*)d_in[6];
    const float* b3    = (const float*)d_in[7];
    float* out = (float*)d_out;
    (void)in_sizes; (void)n_in; (void)out_size;

    cudaFuncSetAttribute(Model_61065845014888_kernel,
                         cudaFuncAttributeMaxDynamicSharedMemorySize, SMEM_BYTES);

    reset_kernel<<<1, 1>>>();
    Model_61065845014888_kernel<<<NCTA, TPB, SMEM_BYTES>>>(
        x, grids, W1, b1, W2, b2, W3, b3, out);
}